// round 8
// baseline (speedup 1.0000x reference)
#include <cuda_runtime.h>
#include <cuda_bf16.h>
#include <cstdint>
#include <math.h>

#define NUM_TOKENS 8192
#define HIDDEN 4096
#define NUM_EXPERTS 8
#define INTER 2048

// ---------------- device scratch (no allocs allowed) ----------------
__device__ int   g_cnt[NUM_EXPERTS];
__device__ int   g_idx[NUM_EXPERTS * NUM_TOKENS];
__device__ float g_inter[(size_t)NUM_TOKENS * INTER];   // 64 MB

// ---------------- routing ----------------
__global__ void zero_cnt_kernel() {
    if (threadIdx.x < NUM_EXPERTS) g_cnt[threadIdx.x] = 0;
}

__global__ void route_kernel(const int* __restrict__ tok32) {
    __shared__ int s_is32;
    if (threadIdx.x == 0) {
        int any = 0;
        #pragma unroll
        for (int j = 1; j < 32; j += 2) any |= tok32[j];
        s_is32 = (any != 0);
    }
    __syncthreads();
    int i = blockIdx.x * blockDim.x + threadIdx.x;
    if (i < NUM_TOKENS) {
        int e;
        if (s_is32) e = tok32[i] & 7;
        else {
            long long t = ((const long long*)tok32)[i];
            e = (int)(t & 7);
        }
        int slot = atomicAdd(&g_cnt[e], 1);
        g_idx[e * NUM_TOKENS + slot] = i;
    }
}

// ---------------- helpers ----------------
// pack two f32 -> half2 reg: lo half = first arg (element k), hi = second (k+1)
__device__ __forceinline__ uint32_t pack_h2(float ek, float ek1) {
    uint32_t r;
    asm("cvt.rn.f16x2.f32 %0, %1, %2;" : "=r"(r) : "f"(ek1), "f"(ek));
    return r;
}

__device__ __forceinline__ void cp16(uint32_t dst, const void* src, bool pred) {
    int sz = pred ? 16 : 0;
    asm volatile("cp.async.cg.shared.global [%0], [%1], 16, %2;\n"
                 :: "r"(dst), "l"(src), "r"(sz));
}
__device__ __forceinline__ void cp_commit() { asm volatile("cp.async.commit_group;\n"); }
__device__ __forceinline__ void cp_wait1()  { asm volatile("cp.async.wait_group 1;\n"); }

__device__ __forceinline__ void mma_fp16(float& c0, float& c1, float& c2, float& c3,
                                         uint32_t a0, uint32_t a1, uint32_t a2, uint32_t a3,
                                         uint32_t b0, uint32_t b1) {
    asm volatile("mma.sync.aligned.m16n8k16.row.col.f32.f16.f16.f32 "
                 "{%0,%1,%2,%3}, {%4,%5,%6,%7}, {%8,%9}, {%0,%1,%2,%3};\n"
                 : "+f"(c0), "+f"(c1), "+f"(c2), "+f"(c3)
                 : "r"(a0), "r"(a1), "r"(a2), "r"(a3), "r"(b0), "r"(b1));
}

// ======================================================================
// GEMM1: gu = X_gathered @ W1[e]  (K=4096), fused silu(gate)*up -> g_inter
// Block tile: 128 (m) x 64 (gate n) + 64 (up n). BK=32 (2 x k16 steps).
// 256 threads = 8 warps: warp_m in {0,1} (64 rows), warp_n in {0..3} (16 cols).
// ======================================================================
#define G1_AST 36      // A smem row stride (floats): 32 + 4 pad
#define G1_BST 72      // B smem row stride (floats): 64 + 8 pad
#define G1_STAGE (128 * G1_AST + 2 * 32 * G1_BST)   // 9216 floats / stage
#define G1_SMEM_BYTES ((2 * G1_STAGE + 128) * 4)    // + 128 ints ridx

__global__ __launch_bounds__(256) void gemm1_kernel(const float* __restrict__ x,
                                                    const float* __restrict__ w1) {
    extern __shared__ float sm[];
    int* ridx = (int*)(sm + 2 * G1_STAGE);

    const int e   = blockIdx.z;
    const int cnt = g_cnt[e];
    const int m0  = blockIdx.y * 128;
    if (m0 >= cnt) return;
    const int n0  = blockIdx.x * 64;

    const int tid = threadIdx.x;
    if (tid < 128) {
        int m = m0 + tid;
        ridx[tid] = (m < cnt) ? g_idx[e * NUM_TOKENS + m] : -1;
    }
    __syncthreads();

    const float* W = w1 + (size_t)e * HIDDEN * (2 * INTER);

    const int wid = tid >> 5, lane = tid & 31;
    const int warp_m = wid & 1, warp_n = wid >> 1;
    const int gid = lane >> 2, tig = lane & 3;

    float cg[4][2][4], cu[4][2][4];
    #pragma unroll
    for (int a = 0; a < 4; a++)
        #pragma unroll
        for (int b = 0; b < 2; b++)
            #pragma unroll
            for (int c = 0; c < 4; c++) { cg[a][b][c] = 0.f; cu[a][b][c] = 0.f; }

    // per-thread A load coords: 4 x float4
    int a_row[4], a_kv[4]; const float* a_src[4]; bool a_pred[4];
    #pragma unroll
    for (int t = 0; t < 4; t++) {
        int vec = tid + t * 256;
        a_row[t] = vec >> 3; a_kv[t] = vec & 7;
        int r = ridx[a_row[t]];
        a_pred[t] = (r >= 0);
        a_src[t] = x + (size_t)(a_pred[t] ? r : 0) * HIDDEN + a_kv[t] * 4;
    }

    uint32_t smem_base = (uint32_t)__cvta_generic_to_shared(sm);

    auto prefetch = [&](int kt, int buf) {
        int k0 = kt * 32;
        #pragma unroll
        for (int t = 0; t < 4; t++)
            cp16(smem_base + (buf * G1_STAGE + a_row[t] * G1_AST + a_kv[t] * 4) * 4,
                 a_src[t] + k0, a_pred[t]);
        #pragma unroll
        for (int t = 0; t < 2; t++) {
            int vec = tid + t * 256;
            int kr = vec >> 4, nv = vec & 15;
            const float* wsrc = W + (size_t)(k0 + kr) * (2 * INTER) + n0 + nv * 4;
            cp16(smem_base + (buf * G1_STAGE + 128 * G1_AST + kr * G1_BST + nv * 4) * 4,
                 wsrc, true);
            cp16(smem_base + (buf * G1_STAGE + 128 * G1_AST + 32 * G1_BST + kr * G1_BST + nv * 4) * 4,
                 wsrc + INTER, true);
        }
    };

    auto compute = [&](int buf) {
        const float* As = sm + buf * G1_STAGE;
        const float* Bg = As + 128 * G1_AST;
        const float* Bu = Bg + 32 * G1_BST;
        #pragma unroll
        for (int ks = 0; ks < 2; ks++) {
            uint32_t a[4][4];
            #pragma unroll
            for (int mt = 0; mt < 4; mt++) {
                int r0 = warp_m * 64 + mt * 16 + gid;
                int c0 = ks * 16 + 2 * tig;
                float2 v0 = *(const float2*)&As[r0 * G1_AST + c0];
                float2 v1 = *(const float2*)&As[(r0 + 8) * G1_AST + c0];
                float2 v2 = *(const float2*)&As[r0 * G1_AST + c0 + 8];
                float2 v3 = *(const float2*)&As[(r0 + 8) * G1_AST + c0 + 8];
                a[mt][0] = pack_h2(v0.x, v0.y);
                a[mt][1] = pack_h2(v1.x, v1.y);
                a[mt][2] = pack_h2(v2.x, v2.y);
                a[mt][3] = pack_h2(v3.x, v3.y);
            }
            uint32_t bg[2][2], bu[2][2];
            #pragma unroll
            for (int nt = 0; nt < 2; nt++) {
                int n = warp_n * 16 + nt * 8 + gid;
                int k = ks * 16 + 2 * tig;
                bg[nt][0] = pack_h2(Bg[k * G1_BST + n],       Bg[(k + 1) * G1_BST + n]);
                bg[nt][1] = pack_h2(Bg[(k + 8) * G1_BST + n], Bg[(k + 9) * G1_BST + n]);
                bu[nt][0] = pack_h2(Bu[k * G1_BST + n],       Bu[(k + 1) * G1_BST + n]);
                bu[nt][1] = pack_h2(Bu[(k + 8) * G1_BST + n], Bu[(k + 9) * G1_BST + n]);
            }
            #pragma unroll
            for (int mt = 0; mt < 4; mt++)
                #pragma unroll
                for (int nt = 0; nt < 2; nt++) {
                    mma_fp16(cg[mt][nt][0], cg[mt][nt][1], cg[mt][nt][2], cg[mt][nt][3],
                             a[mt][0], a[mt][1], a[mt][2], a[mt][3], bg[nt][0], bg[nt][1]);
                    mma_fp16(cu[mt][nt][0], cu[mt][nt][1], cu[mt][nt][2], cu[mt][nt][3],
                             a[mt][0], a[mt][1], a[mt][2], a[mt][3], bu[nt][0], bu[nt][1]);
                }
        }
    };

    const int NK = HIDDEN / 32;   // 128
    prefetch(0, 0);
    cp_commit();
    for (int kt = 0; kt < NK; kt++) {
        int buf = kt & 1;
        if (kt + 1 < NK) prefetch(kt + 1, buf ^ 1);
        cp_commit();
        cp_wait1();
        __syncthreads();
        compute(buf);
        __syncthreads();
    }

    // epilogue: silu(gate) * up -> g_inter[token][col]
    #pragma unroll
    for (int mt = 0; mt < 4; mt++) {
        int lm = warp_m * 64 + mt * 16 + gid;
        int t0 = ridx[lm];
        int t1 = ridx[lm + 8];
        #pragma unroll
        for (int nt = 0; nt < 2; nt++) {
            int col = n0 + warp_n * 16 + nt * 8 + 2 * tig;
            if (t0 >= 0) {
                float g0 = cg[mt][nt][0], u0 = cu[mt][nt][0];
                float g1 = cg[mt][nt][1], u1 = cu[mt][nt][1];
                float2 v;
                v.x = g0 / (1.f + __expf(-g0)) * u0;
                v.y = g1 / (1.f + __expf(-g1)) * u1;
                *(float2*)&g_inter[(size_t)t0 * INTER + col] = v;
            }
            if (t1 >= 0) {
                float g0 = cg[mt][nt][2], u0 = cu[mt][nt][2];
                float g1 = cg[mt][nt][3], u1 = cu[mt][nt][3];
                float2 v;
                v.x = g0 / (1.f + __expf(-g0)) * u0;
                v.y = g1 / (1.f + __expf(-g1)) * u1;
                *(float2*)&g_inter[(size_t)t1 * INTER + col] = v;
            }
        }
    }
}

// ======================================================================
// GEMM2: out = inter_gathered @ W2[e]  (K=2048), scatter rows to out.
// Block tile 128 x 128, BK=32 (2 x k16). warp_m in {0,1}, warp_n in {0..3}.
// ======================================================================
#define G2_AST 36
#define G2_BST 136     // 128 + 8 pad
#define G2_STAGE (128 * G2_AST + 32 * G2_BST)       // 8960 floats
#define G2_SMEM_BYTES ((2 * G2_STAGE + 128) * 4)

__global__ __launch_bounds__(256) void gemm2_kernel(const float* __restrict__ w2,
                                                    float* __restrict__ out) {
    extern __shared__ float sm[];
    int* ridx = (int*)(sm + 2 * G2_STAGE);

    const int e   = blockIdx.z;
    const int cnt = g_cnt[e];
    const int m0  = blockIdx.y * 128;
    if (m0 >= cnt) return;
    const int n0  = blockIdx.x * 128;

    const int tid = threadIdx.x;
    if (tid < 128) {
        int m = m0 + tid;
        ridx[tid] = (m < cnt) ? g_idx[e * NUM_TOKENS + m] : -1;
    }
    __syncthreads();

    const float* W = w2 + (size_t)e * INTER * HIDDEN;

    const int wid = tid >> 5, lane = tid & 31;
    const int warp_m = wid & 1, warp_n = wid >> 1;
    const int gid = lane >> 2, tig = lane & 3;

    float cc[4][4][4];
    #pragma unroll
    for (int a = 0; a < 4; a++)
        #pragma unroll
        for (int b = 0; b < 4; b++)
            #pragma unroll
            for (int c = 0; c < 4; c++) cc[a][b][c] = 0.f;

    int a_row[4], a_kv[4]; const float* a_src[4]; bool a_pred[4];
    #pragma unroll
    for (int t = 0; t < 4; t++) {
        int vec = tid + t * 256;
        a_row[t] = vec >> 3; a_kv[t] = vec & 7;
        int r = ridx[a_row[t]];
        a_pred[t] = (r >= 0);
        a_src[t] = g_inter + (size_t)(a_pred[t] ? r : 0) * INTER + a_kv[t] * 4;
    }

    uint32_t smem_base = (uint32_t)__cvta_generic_to_shared(sm);

    auto prefetch = [&](int kt, int buf) {
        int k0 = kt * 32;
        #pragma unroll
        for (int t = 0; t < 4; t++)
            cp16(smem_base + (buf * G2_STAGE + a_row[t] * G2_AST + a_kv[t] * 4) * 4,
                 a_src[t] + k0, a_pred[t]);
        #pragma unroll
        for (int t = 0; t < 4; t++) {
            int vec = tid + t * 256;
            int kr = vec >> 5, nv = vec & 31;
            cp16(smem_base + (buf * G2_STAGE + 128 * G2_AST + kr * G2_BST + nv * 4) * 4,
                 W + (size_t)(k0 + kr) * HIDDEN + n0 + nv * 4, true);
        }
    };

    auto compute = [&](int buf) {
        const float* As = sm + buf * G2_STAGE;
        const float* Bs = As + 128 * G2_AST;
        #pragma unroll
        for (int ks = 0; ks < 2; ks++) {
            uint32_t a[4][4];
            #pragma unroll
            for (int mt = 0; mt < 4; mt++) {
                int r0 = warp_m * 64 + mt * 16 + gid;
                int c0 = ks * 16 + 2 * tig;
                float2 v0 = *(const float2*)&As[r0 * G2_AST + c0];
                float2 v1 = *(const float2*)&As[(r0 + 8) * G2_AST + c0];
                float2 v2 = *(const float2*)&As[r0 * G2_AST + c0 + 8];
                float2 v3 = *(const float2*)&As[(r0 + 8) * G2_AST + c0 + 8];
                a[mt][0] = pack_h2(v0.x, v0.y);
                a[mt][1] = pack_h2(v1.x, v1.y);
                a[mt][2] = pack_h2(v2.x, v2.y);
                a[mt][3] = pack_h2(v3.x, v3.y);
            }
            uint32_t b[4][2];
            #pragma unroll
            for (int nt = 0; nt < 4; nt++) {
                int n = warp_n * 32 + nt * 8 + gid;
                int k = ks * 16 + 2 * tig;
                b[nt][0] = pack_h2(Bs[k * G2_BST + n],       Bs[(k + 1) * G2_BST + n]);
                b[nt][1] = pack_h2(Bs[(k + 8) * G2_BST + n], Bs[(k + 9) * G2_BST + n]);
            }
            #pragma unroll
            for (int mt = 0; mt < 4; mt++)
                #pragma unroll
                for (int nt = 0; nt < 4; nt++)
                    mma_fp16(cc[mt][nt][0], cc[mt][nt][1], cc[mt][nt][2], cc[mt][nt][3],
                             a[mt][0], a[mt][1], a[mt][2], a[mt][3], b[nt][0], b[nt][1]);
        }
    };

    const int NK = INTER / 32;   // 64
    prefetch(0, 0);
    cp_commit();
    for (int kt = 0; kt < NK; kt++) {
        int buf = kt & 1;
        if (kt + 1 < NK) prefetch(kt + 1, buf ^ 1);
        cp_commit();
        cp_wait1();
        __syncthreads();
        compute(buf);
        __syncthreads();
    }

    // epilogue: scatter to out
    #pragma unroll
    for (int mt = 0; mt < 4; mt++) {
        int lm = warp_m * 64 + mt * 16 + gid;
        int t0 = ridx[lm];
        int t1 = ridx[lm + 8];
        #pragma unroll
        for (int nt = 0; nt < 4; nt++) {
            int col = n0 + warp_n * 32 + nt * 8 + 2 * tig;
            if (t0 >= 0) {
                float2 v = make_float2(cc[mt][nt][0], cc[mt][nt][1]);
                *(float2*)&out[(size_t)t0 * HIDDEN + col] = v;
            }
            if (t1 >= 0) {
                float2 v = make_float2(cc[mt][nt][2], cc[mt][nt][3]);
                *(float2*)&out[(size_t)t1 * HIDDEN + col] = v;
            }
        }
    }
}

// ---------------- launch ----------------
extern "C" void kernel_launch(void* const* d_in, const int* in_sizes, int n_in,
                              void* d_out, int out_size) {
    const float* x  = nullptr;
    const float* w1 = nullptr;
    const float* w2 = nullptr;
    const int*   tok = nullptr;
    for (int i = 0; i < n_in; i++) {
        long long n = in_sizes[i];
        if (n == (long long)NUM_TOKENS) tok = (const int*)d_in[i];
        else if (n == (long long)NUM_TOKENS * HIDDEN) x = (const float*)d_in[i];
        else if (n == (long long)NUM_EXPERTS * HIDDEN * 2 * INTER) w1 = (const float*)d_in[i];
        else if (n == (long long)NUM_EXPERTS * INTER * HIDDEN) w2 = (const float*)d_in[i];
    }
    float* out = (float*)d_out;

    cudaFuncSetAttribute(gemm1_kernel, cudaFuncAttributeMaxDynamicSharedMemorySize, G1_SMEM_BYTES);
    cudaFuncSetAttribute(gemm2_kernel, cudaFuncAttributeMaxDynamicSharedMemorySize, G2_SMEM_BYTES);

    zero_cnt_kernel<<<1, 32>>>();
    route_kernel<<<NUM_TOKENS / 256, 256>>>(tok);

    // gemm1: n-tiles (2048/64=32) x m-tiles (64) x experts (8)
    gemm1_kernel<<<dim3(32, 64, 8), 256, G1_SMEM_BYTES>>>(x, w1);
    // gemm2: n-tiles (4096/128=32) x m-tiles (64) x experts (8)
    gemm2_kernel<<<dim3(32, 64, 8), 256, G2_SMEM_BYTES>>>(w2, out);
}

// round 9
// speedup vs baseline: 1.9650x; 1.9650x over previous
#include <cuda_runtime.h>
#include <cuda_fp16.h>
#include <cstdint>
#include <math.h>

#define NUM_TOKENS 8192
#define HIDDEN 4096
#define NUM_EXPERTS 8
#define INTER 2048

// ---------------- device scratch (no allocs allowed) ----------------
__device__ int    g_cnt[NUM_EXPERTS];
__device__ int    g_idx[NUM_EXPERTS * NUM_TOKENS];
__device__ __half g_xh[(size_t)NUM_TOKENS * HIDDEN];                  // 67 MB
__device__ __half g_w1c[(size_t)NUM_EXPERTS * 2 * INTER * HIDDEN];    // 268 MB, [e][2I][H]
__device__ __half g_w2c[(size_t)NUM_EXPERTS * HIDDEN * INTER];        // 134 MB, [e][H][I]
__device__ __half g_interh[(size_t)NUM_TOKENS * INTER];               // 33 MB

// ---------------- routing ----------------
__global__ void zero_cnt_kernel() {
    if (threadIdx.x < NUM_EXPERTS) g_cnt[threadIdx.x] = 0;
}

__global__ void route_kernel(const int* __restrict__ tok32) {
    __shared__ int s_is32;
    if (threadIdx.x == 0) {
        int any = 0;
        #pragma unroll
        for (int j = 1; j < 32; j += 2) any |= tok32[j];
        s_is32 = (any != 0);
    }
    __syncthreads();
    int i = blockIdx.x * blockDim.x + threadIdx.x;
    if (i < NUM_TOKENS) {
        int e;
        if (s_is32) e = tok32[i] & 7;
        else {
            long long t = ((const long long*)tok32)[i];
            e = (int)(t & 7);
        }
        int slot = atomicAdd(&g_cnt[e], 1);
        g_idx[e * NUM_TOKENS + slot] = i;
    }
}

// ---------------- preprocessing: convert / transpose to fp16 ----------------
__global__ void convert_x_kernel(const float4* __restrict__ x4) {
    int i = blockIdx.x * blockDim.x + threadIdx.x;
    #pragma unroll
    for (int t = 0; t < 4; t++) {
        size_t idx = (size_t)i + (size_t)t * 8192 * 256;
        float4 v = x4[idx];
        __half2 h0 = __floats2half2_rn(v.x, v.y);
        __half2 h1 = __floats2half2_rn(v.z, v.w);
        uint2 u;
        u.x = *(uint32_t*)&h0;
        u.y = *(uint32_t*)&h1;
        *(uint2*)&g_xh[idx * 4] = u;
    }
}

// w1: [e][H][2I] fp32 -> g_w1c [e][2I][H] fp16
__global__ void transpose_w1_kernel(const float* __restrict__ w1) {
    __shared__ float tile[32][33];
    int e = blockIdx.z;
    const float* in = w1 + (size_t)e * HIDDEN * (2 * INTER);
    __half* out = g_w1c + (size_t)e * (2 * INTER) * HIDDEN;
    int r0 = blockIdx.y * 32;   // H
    int c0 = blockIdx.x * 32;   // 2I
    int x = threadIdx.x, y = threadIdx.y;
    #pragma unroll
    for (int j = 0; j < 32; j += 8)
        tile[y + j][x] = in[(size_t)(r0 + y + j) * (2 * INTER) + c0 + x];
    __syncthreads();
    #pragma unroll
    for (int j = 0; j < 32; j += 8)
        out[(size_t)(c0 + y + j) * HIDDEN + r0 + x] = __float2half(tile[x][y + j]);
}

// w2: [e][I][H] fp32 -> g_w2c [e][H][I] fp16
__global__ void transpose_w2_kernel(const float* __restrict__ w2) {
    __shared__ float tile[32][33];
    int e = blockIdx.z;
    const float* in = w2 + (size_t)e * INTER * HIDDEN;
    __half* out = g_w2c + (size_t)e * HIDDEN * INTER;
    int r0 = blockIdx.y * 32;   // I
    int c0 = blockIdx.x * 32;   // H
    int x = threadIdx.x, y = threadIdx.y;
    #pragma unroll
    for (int j = 0; j < 32; j += 8)
        tile[y + j][x] = in[(size_t)(r0 + y + j) * HIDDEN + c0 + x];
    __syncthreads();
    #pragma unroll
    for (int j = 0; j < 32; j += 8)
        out[(size_t)(c0 + y + j) * INTER + r0 + x] = __float2half(tile[x][y + j]);
}

// ---------------- helpers ----------------
__device__ __forceinline__ void cp16(uint32_t dst, const void* src, bool pred) {
    int sz = pred ? 16 : 0;
    asm volatile("cp.async.cg.shared.global [%0], [%1], 16, %2;\n"
                 :: "r"(dst), "l"(src), "r"(sz));
}
__device__ __forceinline__ void cp_commit() { asm volatile("cp.async.commit_group;\n"); }
__device__ __forceinline__ void cp_wait1()  { asm volatile("cp.async.wait_group 1;\n"); }

__device__ __forceinline__ void mma_fp16(float& c0, float& c1, float& c2, float& c3,
                                         uint32_t a0, uint32_t a1, uint32_t a2, uint32_t a3,
                                         uint32_t b0, uint32_t b1) {
    asm volatile("mma.sync.aligned.m16n8k16.row.col.f32.f16.f16.f32 "
                 "{%0,%1,%2,%3}, {%4,%5,%6,%7}, {%8,%9}, {%0,%1,%2,%3};\n"
                 : "+f"(c0), "+f"(c1), "+f"(c2), "+f"(c3)
                 : "r"(a0), "r"(a1), "r"(a2), "r"(a3), "r"(b0), "r"(b1));
}

#define U32AT(p) (*(const uint32_t*)&(p))

// ---------------- shared geometry (both GEMMs) ----------------
// Stage = A tile (128 rows x 64 halves, stride 72) + B tile (128 rows x 64, stride 72)
// 9216 + 9216 = 18432 halves = 36864 B per stage; double buffered = 73728 B (+512 ridx)
#define AST      72
#define TILEH    (128 * AST)          // 9216 halves
#define STAGEH   (2 * TILEH)          // 18432 halves
#define G_SMEM   (2 * STAGEH * 2 + 512)

// ======================================================================
// GEMM1: gu = Xh_gathered @ W1c[e]^T slices (K=4096, BK=64), silu*up -> g_interh
// Tile: M=128, gate N=64 + up N=64. 8 warps: warp_m{0,1} x warp_n{0..3}.
// ======================================================================
__global__ __launch_bounds__(256) void gemm1_kernel() {
    extern __shared__ __half smh[];
    int* ridx = (int*)(smh + 2 * STAGEH);

    const int e   = blockIdx.z;
    const int cnt = g_cnt[e];
    const int m0  = blockIdx.y * 128;
    if (m0 >= cnt) return;
    const int n0  = blockIdx.x * 64;

    const int tid = threadIdx.x;
    if (tid < 128) {
        int m = m0 + tid;
        ridx[tid] = (m < cnt) ? g_idx[e * NUM_TOKENS + m] : -1;
    }
    __syncthreads();

    const __half* W = g_w1c + (size_t)e * (2 * INTER) * HIDDEN;

    const int wid = tid >> 5, lane = tid & 31;
    const int warp_m = wid & 1, warp_n = wid >> 1;
    const int gid = lane >> 2, tig = lane & 3;

    float cg[4][2][4], cu[4][2][4];
    #pragma unroll
    for (int a = 0; a < 4; a++)
        #pragma unroll
        for (int b = 0; b < 2; b++)
            #pragma unroll
            for (int c = 0; c < 4; c++) { cg[a][b][c] = 0.f; cu[a][b][c] = 0.f; }

    // A: 128 rows x 64 halves = 1024 x 8-half chunks -> 4 per thread
    const __half* asrc[4]; bool apred[4]; int arow[4], acv[4];
    #pragma unroll
    for (int t = 0; t < 4; t++) {
        int vec = tid + t * 256;
        arow[t] = vec >> 3; acv[t] = vec & 7;
        int r = ridx[arow[t]];
        apred[t] = (r >= 0);
        asrc[t] = g_xh + (size_t)(apred[t] ? r : 0) * HIDDEN + acv[t] * 8;
    }
    // B: rows 0..63 = gate cols n0.., rows 64..127 = up cols INTER+n0..
    const __half* bsrc[4]; int brow[4], bcv[4];
    #pragma unroll
    for (int t = 0; t < 4; t++) {
        int vec = tid + t * 256;
        brow[t] = vec >> 3; bcv[t] = vec & 7;
        int grow = (brow[t] < 64) ? (n0 + brow[t]) : (INTER + n0 + (brow[t] - 64));
        bsrc[t] = W + (size_t)grow * HIDDEN + bcv[t] * 8;
    }

    uint32_t sb = (uint32_t)__cvta_generic_to_shared(smh);

    auto prefetch = [&](int kt, int buf) {
        int k0 = kt * 64;
        #pragma unroll
        for (int t = 0; t < 4; t++)
            cp16(sb + (buf * STAGEH + arow[t] * AST + acv[t] * 8) * 2, asrc[t] + k0, apred[t]);
        #pragma unroll
        for (int t = 0; t < 4; t++)
            cp16(sb + (buf * STAGEH + TILEH + brow[t] * AST + bcv[t] * 8) * 2, bsrc[t] + k0, true);
    };

    auto compute = [&](int buf) {
        const __half* As = smh + buf * STAGEH;
        const __half* Bs = As + TILEH;
        #pragma unroll
        for (int ks = 0; ks < 4; ks++) {
            int c0 = ks * 16 + 2 * tig;
            uint32_t a[4][4];
            #pragma unroll
            for (int mt = 0; mt < 4; mt++) {
                int r0 = warp_m * 64 + mt * 16 + gid;
                a[mt][0] = U32AT(As[r0 * AST + c0]);
                a[mt][1] = U32AT(As[(r0 + 8) * AST + c0]);
                a[mt][2] = U32AT(As[r0 * AST + c0 + 8]);
                a[mt][3] = U32AT(As[(r0 + 8) * AST + c0 + 8]);
            }
            uint32_t bg[2][2], bu[2][2];
            #pragma unroll
            for (int nt = 0; nt < 2; nt++) {
                int n = warp_n * 16 + nt * 8 + gid;
                bg[nt][0] = U32AT(Bs[n * AST + c0]);
                bg[nt][1] = U32AT(Bs[n * AST + c0 + 8]);
                bu[nt][0] = U32AT(Bs[(64 + n) * AST + c0]);
                bu[nt][1] = U32AT(Bs[(64 + n) * AST + c0 + 8]);
            }
            #pragma unroll
            for (int mt = 0; mt < 4; mt++)
                #pragma unroll
                for (int nt = 0; nt < 2; nt++) {
                    mma_fp16(cg[mt][nt][0], cg[mt][nt][1], cg[mt][nt][2], cg[mt][nt][3],
                             a[mt][0], a[mt][1], a[mt][2], a[mt][3], bg[nt][0], bg[nt][1]);
                    mma_fp16(cu[mt][nt][0], cu[mt][nt][1], cu[mt][nt][2], cu[mt][nt][3],
                             a[mt][0], a[mt][1], a[mt][2], a[mt][3], bu[nt][0], bu[nt][1]);
                }
        }
    };

    const int NK = HIDDEN / 64;   // 64
    prefetch(0, 0);
    cp_commit();
    for (int kt = 0; kt < NK; kt++) {
        int buf = kt & 1;
        if (kt + 1 < NK) prefetch(kt + 1, buf ^ 1);
        cp_commit();
        cp_wait1();
        __syncthreads();
        compute(buf);
        __syncthreads();
    }

    // epilogue: silu(gate)*up -> g_interh (fp16)
    #pragma unroll
    for (int mt = 0; mt < 4; mt++) {
        int lm = warp_m * 64 + mt * 16 + gid;
        int t0 = ridx[lm];
        int t1 = ridx[lm + 8];
        #pragma unroll
        for (int nt = 0; nt < 2; nt++) {
            int col = n0 + warp_n * 16 + nt * 8 + 2 * tig;
            if (t0 >= 0) {
                float g0 = cg[mt][nt][0], u0 = cu[mt][nt][0];
                float g1 = cg[mt][nt][1], u1 = cu[mt][nt][1];
                float v0 = g0 / (1.f + __expf(-g0)) * u0;
                float v1 = g1 / (1.f + __expf(-g1)) * u1;
                *(__half2*)&g_interh[(size_t)t0 * INTER + col] = __floats2half2_rn(v0, v1);
            }
            if (t1 >= 0) {
                float g0 = cg[mt][nt][2], u0 = cu[mt][nt][2];
                float g1 = cg[mt][nt][3], u1 = cu[mt][nt][3];
                float v0 = g0 / (1.f + __expf(-g0)) * u0;
                float v1 = g1 / (1.f + __expf(-g1)) * u1;
                *(__half2*)&g_interh[(size_t)t1 * INTER + col] = __floats2half2_rn(v0, v1);
            }
        }
    }
}

// ======================================================================
// GEMM2: out = interh_gathered @ W2c[e]^T (K=2048, BK=64), scatter fp32 rows.
// Tile 128 x 128. 8 warps: warp_m{0,1} x warp_n{0..3} (32 cols each).
// ======================================================================
__global__ __launch_bounds__(256) void gemm2_kernel(float* __restrict__ out) {
    extern __shared__ __half smh[];
    int* ridx = (int*)(smh + 2 * STAGEH);

    const int e   = blockIdx.z;
    const int cnt = g_cnt[e];
    const int m0  = blockIdx.y * 128;
    if (m0 >= cnt) return;
    const int n0  = blockIdx.x * 128;

    const int tid = threadIdx.x;
    if (tid < 128) {
        int m = m0 + tid;
        ridx[tid] = (m < cnt) ? g_idx[e * NUM_TOKENS + m] : -1;
    }
    __syncthreads();

    const __half* W = g_w2c + (size_t)e * HIDDEN * INTER;

    const int wid = tid >> 5, lane = tid & 31;
    const int warp_m = wid & 1, warp_n = wid >> 1;
    const int gid = lane >> 2, tig = lane & 3;

    float cc[4][4][4];
    #pragma unroll
    for (int a = 0; a < 4; a++)
        #pragma unroll
        for (int b = 0; b < 4; b++)
            #pragma unroll
            for (int c = 0; c < 4; c++) cc[a][b][c] = 0.f;

    const __half* asrc[4]; bool apred[4]; int arow[4], acv[4];
    #pragma unroll
    for (int t = 0; t < 4; t++) {
        int vec = tid + t * 256;
        arow[t] = vec >> 3; acv[t] = vec & 7;
        int r = ridx[arow[t]];
        apred[t] = (r >= 0);
        asrc[t] = g_interh + (size_t)(apred[t] ? r : 0) * INTER + acv[t] * 8;
    }
    const __half* bsrc[4]; int brow[4], bcv[4];
    #pragma unroll
    for (int t = 0; t < 4; t++) {
        int vec = tid + t * 256;
        brow[t] = vec >> 3; bcv[t] = vec & 7;
        bsrc[t] = W + (size_t)(n0 + brow[t]) * INTER + bcv[t] * 8;
    }

    uint32_t sb = (uint32_t)__cvta_generic_to_shared(smh);

    auto prefetch = [&](int kt, int buf) {
        int k0 = kt * 64;
        #pragma unroll
        for (int t = 0; t < 4; t++)
            cp16(sb + (buf * STAGEH + arow[t] * AST + acv[t] * 8) * 2, asrc[t] + k0, apred[t]);
        #pragma unroll
        for (int t = 0; t < 4; t++)
            cp16(sb + (buf * STAGEH + TILEH + brow[t] * AST + bcv[t] * 8) * 2, bsrc[t] + k0, true);
    };

    auto compute = [&](int buf) {
        const __half* As = smh + buf * STAGEH;
        const __half* Bs = As + TILEH;
        #pragma unroll
        for (int ks = 0; ks < 4; ks++) {
            int c0 = ks * 16 + 2 * tig;
            uint32_t a[4][4];
            #pragma unroll
            for (int mt = 0; mt < 4; mt++) {
                int r0 = warp_m * 64 + mt * 16 + gid;
                a[mt][0] = U32AT(As[r0 * AST + c0]);
                a[mt][1] = U32AT(As[(r0 + 8) * AST + c0]);
                a[mt][2] = U32AT(As[r0 * AST + c0 + 8]);
                a[mt][3] = U32AT(As[(r0 + 8) * AST + c0 + 8]);
            }
            uint32_t b[4][2];
            #pragma unroll
            for (int nt = 0; nt < 4; nt++) {
                int n = warp_n * 32 + nt * 8 + gid;
                b[nt][0] = U32AT(Bs[n * AST + c0]);
                b[nt][1] = U32AT(Bs[n * AST + c0 + 8]);
            }
            #pragma unroll
            for (int mt = 0; mt < 4; mt++)
                #pragma unroll
                for (int nt = 0; nt < 4; nt++)
                    mma_fp16(cc[mt][nt][0], cc[mt][nt][1], cc[mt][nt][2], cc[mt][nt][3],
                             a[mt][0], a[mt][1], a[mt][2], a[mt][3], b[nt][0], b[nt][1]);
        }
    };

    const int NK = INTER / 64;   // 32
    prefetch(0, 0);
    cp_commit();
    for (int kt = 0; kt < NK; kt++) {
        int buf = kt & 1;
        if (kt + 1 < NK) prefetch(kt + 1, buf ^ 1);
        cp_commit();
        cp_wait1();
        __syncthreads();
        compute(buf);
        __syncthreads();
    }

    // epilogue: scatter fp32 rows to out
    #pragma unroll
    for (int mt = 0; mt < 4; mt++) {
        int lm = warp_m * 64 + mt * 16 + gid;
        int t0 = ridx[lm];
        int t1 = ridx[lm + 8];
        #pragma unroll
        for (int nt = 0; nt < 4; nt++) {
            int col = n0 + warp_n * 32 + nt * 8 + 2 * tig;
            if (t0 >= 0) {
                float2 v = make_float2(cc[mt][nt][0], cc[mt][nt][1]);
                *(float2*)&out[(size_t)t0 * HIDDEN + col] = v;
            }
            if (t1 >= 0) {
                float2 v = make_float2(cc[mt][nt][2], cc[mt][nt][3]);
                *(float2*)&out[(size_t)t1 * HIDDEN + col] = v;
            }
        }
    }
}

// ---------------- launch ----------------
extern "C" void kernel_launch(void* const* d_in, const int* in_sizes, int n_in,
                              void* d_out, int out_size) {
    const float* x  = nullptr;
    const float* w1 = nullptr;
    const float* w2 = nullptr;
    const int*   tok = nullptr;
    for (int i = 0; i < n_in; i++) {
        long long n = in_sizes[i];
        if (n == (long long)NUM_TOKENS) tok = (const int*)d_in[i];
        else if (n == (long long)NUM_TOKENS * HIDDEN) x = (const float*)d_in[i];
        else if (n == (long long)NUM_EXPERTS * HIDDEN * 2 * INTER) w1 = (const float*)d_in[i];
        else if (n == (long long)NUM_EXPERTS * INTER * HIDDEN) w2 = (const float*)d_in[i];
    }
    float* out = (float*)d_out;

    cudaFuncSetAttribute(gemm1_kernel, cudaFuncAttributeMaxDynamicSharedMemorySize, G_SMEM);
    cudaFuncSetAttribute(gemm2_kernel, cudaFuncAttributeMaxDynamicSharedMemorySize, G_SMEM);

    zero_cnt_kernel<<<1, 32>>>();
    route_kernel<<<NUM_TOKENS / 256, 256>>>(tok);

    // preprocessing: fp16 convert (+ weight transposes to [N][K])
    convert_x_kernel<<<8192, 256>>>((const float4*)x);
    transpose_w1_kernel<<<dim3(128, 128, 8), dim3(32, 8)>>>(w1);
    transpose_w2_kernel<<<dim3(128, 64, 8), dim3(32, 8)>>>(w2);

    // gemm1: n-tiles (2048/64=32) x m-tiles (64) x experts (8)
    gemm1_kernel<<<dim3(32, 64, 8), 256, G_SMEM>>>();
    // gemm2: n-tiles (4096/128=32) x m-tiles (64) x experts (8)
    gemm2_kernel<<<dim3(32, 64, 8), 256, G_SMEM>>>(out);
}

// round 11
// speedup vs baseline: 2.0559x; 1.0462x over previous
#include <cuda_runtime.h>
#include <cuda_fp16.h>
#include <cstdint>
#include <math.h>

#define NUM_TOKENS 8192
#define HIDDEN 4096
#define NUM_EXPERTS 8
#define INTER 2048

// ---------------- device scratch (no allocs allowed) ----------------
__device__ int    g_cnt[NUM_EXPERTS];
__device__ int    g_idx[NUM_EXPERTS * NUM_TOKENS];
__device__ __half g_xh[(size_t)NUM_TOKENS * HIDDEN];                  // 67 MB
__device__ __half g_w1c[(size_t)NUM_EXPERTS * 2 * INTER * HIDDEN];    // 268 MB, [e][2I][H]
__device__ __half g_w2c[(size_t)NUM_EXPERTS * HIDDEN * INTER];        // 134 MB, [e][H][I]
__device__ __half g_interh[(size_t)NUM_TOKENS * INTER];               // 33 MB

// ---------------- routing ----------------
__global__ void zero_cnt_kernel() {
    if (threadIdx.x < NUM_EXPERTS) g_cnt[threadIdx.x] = 0;
}

__global__ void route_kernel(const int* __restrict__ tok32) {
    __shared__ int s_is32;
    if (threadIdx.x == 0) {
        int any = 0;
        #pragma unroll
        for (int j = 1; j < 32; j += 2) any |= tok32[j];
        s_is32 = (any != 0);
    }
    __syncthreads();
    int i = blockIdx.x * blockDim.x + threadIdx.x;
    if (i < NUM_TOKENS) {
        int e;
        if (s_is32) e = tok32[i] & 7;
        else {
            long long t = ((const long long*)tok32)[i];
            e = (int)(t & 7);
        }
        int slot = atomicAdd(&g_cnt[e], 1);
        g_idx[e * NUM_TOKENS + slot] = i;
    }
}

// ---------------- preprocessing: convert / transpose to fp16 ----------------
__global__ void convert_x_kernel(const float4* __restrict__ x4) {
    int i = blockIdx.x * blockDim.x + threadIdx.x;
    #pragma unroll
    for (int t = 0; t < 4; t++) {
        size_t idx = (size_t)i + (size_t)t * 8192 * 256;
        float4 v = x4[idx];
        __half2 h0 = __floats2half2_rn(v.x, v.y);
        __half2 h1 = __floats2half2_rn(v.z, v.w);
        uint2 u;
        u.x = *(uint32_t*)&h0;
        u.y = *(uint32_t*)&h1;
        *(uint2*)&g_xh[idx * 4] = u;
    }
}

// 64x64 fp32->fp16 transpose tile; 128B-wide fp16 writes.
// in: [rows R][cols C] fp32 at (r0, c0); out: [C][R] fp16.
__device__ __forceinline__ void transpose_tile64(const float* __restrict__ in, __half* __restrict__ out,
                                                 int in_cols, int out_cols, int r0, int c0) {
    __shared__ float tile[64][65];
    int x = threadIdx.x, y = threadIdx.y;   // 32 x 8
    #pragma unroll
    for (int j = 0; j < 64; j += 8) {
        const float* src = in + (size_t)(r0 + y + j) * in_cols + c0;
        tile[y + j][x]      = src[x];
        tile[y + j][x + 32] = src[x + 32];
    }
    __syncthreads();
    #pragma unroll
    for (int j = 0; j < 64; j += 8) {
        int c = c0 + y + j;
        __half2 h = __floats2half2_rn(tile[2 * x][y + j], tile[2 * x + 1][y + j]);
        *(__half2*)&out[(size_t)c * out_cols + r0 + 2 * x] = h;
    }
}

// w1: [e][H][2I] fp32 -> g_w1c [e][2I][H] fp16
__global__ void transpose_w1_kernel(const float* __restrict__ w1) {
    int e = blockIdx.z;
    transpose_tile64(w1 + (size_t)e * HIDDEN * (2 * INTER),
                     g_w1c + (size_t)e * (2 * INTER) * HIDDEN,
                     2 * INTER, HIDDEN, blockIdx.y * 64, blockIdx.x * 64);
}

// w2: [e][I][H] fp32 -> g_w2c [e][H][I] fp16
__global__ void transpose_w2_kernel(const float* __restrict__ w2) {
    int e = blockIdx.z;
    transpose_tile64(w2 + (size_t)e * INTER * HIDDEN,
                     g_w2c + (size_t)e * HIDDEN * INTER,
                     HIDDEN, INTER, blockIdx.y * 64, blockIdx.x * 64);
}

// ---------------- helpers ----------------
__device__ __forceinline__ void cp16(uint32_t dst, const void* src, bool pred) {
    int sz = pred ? 16 : 0;
    asm volatile("cp.async.cg.shared.global [%0], [%1], 16, %2;\n"
                 :: "r"(dst), "l"(src), "r"(sz));
}
__device__ __forceinline__ void cp_commit() { asm volatile("cp.async.commit_group;\n"); }
__device__ __forceinline__ void cp_wait2()  { asm volatile("cp.async.wait_group 2;\n"); }

__device__ __forceinline__ void mma_fp16(float& c0, float& c1, float& c2, float& c3,
                                         uint32_t a0, uint32_t a1, uint32_t a2, uint32_t a3,
                                         uint32_t b0, uint32_t b1) {
    asm volatile("mma.sync.aligned.m16n8k16.row.col.f32.f16.f16.f32 "
                 "{%0,%1,%2,%3}, {%4,%5,%6,%7}, {%8,%9}, {%0,%1,%2,%3};\n"
                 : "+f"(c0), "+f"(c1), "+f"(c2), "+f"(c3)
                 : "r"(a0), "r"(a1), "r"(a2), "r"(a3), "r"(b0), "r"(b1));
}

#define LDSM4(r0, r1, r2, r3, addr) \
    asm volatile("ldmatrix.sync.aligned.m8n8.x4.shared.b16 {%0,%1,%2,%3}, [%4];" \
                 : "=r"(r0), "=r"(r1), "=r"(r2), "=r"(r3) : "r"(addr))

// ---------------- shared geometry (both GEMMs) ----------------
// Stage = A tile (128 x 64 halves, stride 72) + B tile (128 x 64, stride 72)
#define AST      72
#define TILEH    (128 * AST)          // 9216 halves
#define STAGEH   (2 * TILEH)          // 18432 halves = 36864 B
#define NSTAGE   3
#define G_SMEM   (NSTAGE * STAGEH * 2 + 512)

// ======================================================================
// GEMM1: gu = Xh_gathered @ W1c[e]^T (K=4096, BK=64), silu*up -> g_interh
// Tile: M=128, gate N=64 + up N=64. 8 warps: warp_m{0,1} x warp_n{0..3}.
// ======================================================================
__global__ __launch_bounds__(256) void gemm1_kernel() {
    extern __shared__ __half smh[];
    int* ridx = (int*)(smh + NSTAGE * STAGEH);

    const int e   = blockIdx.z;
    const int cnt = g_cnt[e];
    const int m0  = blockIdx.y * 128;
    if (m0 >= cnt) return;
    const int n0  = blockIdx.x * 64;

    const int tid = threadIdx.x;
    if (tid < 128) {
        int m = m0 + tid;
        ridx[tid] = (m < cnt) ? g_idx[e * NUM_TOKENS + m] : -1;
    }
    __syncthreads();

    const __half* W = g_w1c + (size_t)e * (2 * INTER) * HIDDEN;

    const int wid = tid >> 5, lane = tid & 31;
    const int warp_m = wid & 1, warp_n = wid >> 1;
    const int gid = lane >> 2, tig = lane & 3;

    float cg[4][2][4], cu[4][2][4];
    #pragma unroll
    for (int a = 0; a < 4; a++)
        #pragma unroll
        for (int b = 0; b < 2; b++)
            #pragma unroll
            for (int c = 0; c < 4; c++) { cg[a][b][c] = 0.f; cu[a][b][c] = 0.f; }

    const __half* asrc[4]; bool apred[4]; int arow[4], acv[4];
    #pragma unroll
    for (int t = 0; t < 4; t++) {
        int vec = tid + t * 256;
        arow[t] = vec >> 3; acv[t] = vec & 7;
        int r = ridx[arow[t]];
        apred[t] = (r >= 0);
        asrc[t] = g_xh + (size_t)(apred[t] ? r : 0) * HIDDEN + acv[t] * 8;
    }
    const __half* bsrc[4]; int brow[4], bcv[4];
    #pragma unroll
    for (int t = 0; t < 4; t++) {
        int vec = tid + t * 256;
        brow[t] = vec >> 3; bcv[t] = vec & 7;
        int grow = (brow[t] < 64) ? (n0 + brow[t]) : (INTER + n0 + (brow[t] - 64));
        bsrc[t] = W + (size_t)grow * HIDDEN + bcv[t] * 8;
    }

    uint32_t sb = (uint32_t)__cvta_generic_to_shared(smh);

    auto prefetch = [&](int kt, int buf) {
        int k0 = kt * 64;
        #pragma unroll
        for (int t = 0; t < 4; t++)
            cp16(sb + (buf * STAGEH + arow[t] * AST + acv[t] * 8) * 2, asrc[t] + k0, apred[t]);
        #pragma unroll
        for (int t = 0; t < 4; t++)
            cp16(sb + (buf * STAGEH + TILEH + brow[t] * AST + bcv[t] * 8) * 2, bsrc[t] + k0, true);
    };

    // ldmatrix lane-dependent offsets (halves*2 = bytes)
    const uint32_t aoff = ((warp_m * 64 + (lane & 15)) * AST + (lane >> 4) * 8) * 2;
    const uint32_t boff = ((warp_n * 16 + (lane >> 4) * 8 + (lane & 7)) * AST + ((lane >> 3) & 1) * 8) * 2;

    auto compute = [&](int buf) {
        uint32_t abase = sb + buf * STAGEH * 2 + aoff;
        uint32_t bbase = sb + (buf * STAGEH + TILEH) * 2 + boff;
        #pragma unroll
        for (int ks = 0; ks < 4; ks++) {
            uint32_t koff = ks * 16 * 2;
            uint32_t a[4][4];
            #pragma unroll
            for (int mt = 0; mt < 4; mt++)
                LDSM4(a[mt][0], a[mt][1], a[mt][2], a[mt][3],
                      abase + mt * 16 * AST * 2 + koff);
            uint32_t bg[2][2], bu[2][2];
            LDSM4(bg[0][0], bg[0][1], bg[1][0], bg[1][1], bbase + koff);
            LDSM4(bu[0][0], bu[0][1], bu[1][0], bu[1][1], bbase + 64 * AST * 2 + koff);
            #pragma unroll
            for (int mt = 0; mt < 4; mt++)
                #pragma unroll
                for (int nt = 0; nt < 2; nt++) {
                    mma_fp16(cg[mt][nt][0], cg[mt][nt][1], cg[mt][nt][2], cg[mt][nt][3],
                             a[mt][0], a[mt][1], a[mt][2], a[mt][3], bg[nt][0], bg[nt][1]);
                    mma_fp16(cu[mt][nt][0], cu[mt][nt][1], cu[mt][nt][2], cu[mt][nt][3],
                             a[mt][0], a[mt][1], a[mt][2], a[mt][3], bu[nt][0], bu[nt][1]);
                }
        }
    };

    const int NK = HIDDEN / 64;   // 64
    prefetch(0, 0); cp_commit();
    prefetch(1, 1); cp_commit();
    for (int kt = 0; kt < NK; kt++) {
        if (kt + 2 < NK) prefetch(kt + 2, (kt + 2) % NSTAGE);
        cp_commit();
        cp_wait2();
        __syncthreads();
        compute(kt % NSTAGE);
        __syncthreads();
    }

    // epilogue: silu(gate)*up -> g_interh (fp16)
    #pragma unroll
    for (int mt = 0; mt < 4; mt++) {
        int lm = warp_m * 64 + mt * 16 + gid;
        int t0 = ridx[lm];
        int t1 = ridx[lm + 8];
        #pragma unroll
        for (int nt = 0; nt < 2; nt++) {
            int col = n0 + warp_n * 16 + nt * 8 + 2 * tig;
            if (t0 >= 0) {
                float g0 = cg[mt][nt][0], u0 = cu[mt][nt][0];
                float g1 = cg[mt][nt][1], u1 = cu[mt][nt][1];
                float v0 = g0 / (1.f + __expf(-g0)) * u0;
                float v1 = g1 / (1.f + __expf(-g1)) * u1;
                *(__half2*)&g_interh[(size_t)t0 * INTER + col] = __floats2half2_rn(v0, v1);
            }
            if (t1 >= 0) {
                float g0 = cg[mt][nt][2], u0 = cu[mt][nt][2];
                float g1 = cg[mt][nt][3], u1 = cu[mt][nt][3];
                float v0 = g0 / (1.f + __expf(-g0)) * u0;
                float v1 = g1 / (1.f + __expf(-g1)) * u1;
                *(__half2*)&g_interh[(size_t)t1 * INTER + col] = __floats2half2_rn(v0, v1);
            }
        }
    }
}

// ======================================================================
// GEMM2: out = interh_gathered @ W2c[e]^T (K=2048, BK=64), scatter fp32 rows.
// Tile 128 x 128. 8 warps: warp_m{0,1} x warp_n{0..3} (32 cols each).
// ======================================================================
__global__ __launch_bounds__(256) void gemm2_kernel(float* __restrict__ out) {
    extern __shared__ __half smh[];
    int* ridx = (int*)(smh + NSTAGE * STAGEH);

    const int e   = blockIdx.z;
    const int cnt = g_cnt[e];
    const int m0  = blockIdx.y * 128;
    if (m0 >= cnt) return;
    const int n0  = blockIdx.x * 128;

    const int tid = threadIdx.x;
    if (tid < 128) {
        int m = m0 + tid;
        ridx[tid] = (m < cnt) ? g_idx[e * NUM_TOKENS + m] : -1;
    }
    __syncthreads();

    const __half* W = g_w2c + (size_t)e * HIDDEN * INTER;

    const int wid = tid >> 5, lane = tid & 31;
    const int warp_m = wid & 1, warp_n = wid >> 1;
    const int gid = lane >> 2, tig = lane & 3;

    float cc[4][4][4];
    #pragma unroll
    for (int a = 0; a < 4; a++)
        #pragma unroll
        for (int b = 0; b < 4; b++)
            #pragma unroll
            for (int c = 0; c < 4; c++) cc[a][b][c] = 0.f;

    const __half* asrc[4]; bool apred[4]; int arow[4], acv[4];
    #pragma unroll
    for (int t = 0; t < 4; t++) {
        int vec = tid + t * 256;
        arow[t] = vec >> 3; acv[t] = vec & 7;
        int r = ridx[arow[t]];
        apred[t] = (r >= 0);
        asrc[t] = g_interh + (size_t)(apred[t] ? r : 0) * INTER + acv[t] * 8;
    }
    const __half* bsrc[4]; int brow[4], bcv[4];
    #pragma unroll
    for (int t = 0; t < 4; t++) {
        int vec = tid + t * 256;
        brow[t] = vec >> 3; bcv[t] = vec & 7;
        bsrc[t] = W + (size_t)(n0 + brow[t]) * INTER + bcv[t] * 8;
    }

    uint32_t sb = (uint32_t)__cvta_generic_to_shared(smh);

    auto prefetch = [&](int kt, int buf) {
        int k0 = kt * 64;
        #pragma unroll
        for (int t = 0; t < 4; t++)
            cp16(sb + (buf * STAGEH + arow[t] * AST + acv[t] * 8) * 2, asrc[t] + k0, apred[t]);
        #pragma unroll
        for (int t = 0; t < 4; t++)
            cp16(sb + (buf * STAGEH + TILEH + brow[t] * AST + bcv[t] * 8) * 2, bsrc[t] + k0, true);
    };

    const uint32_t aoff = ((warp_m * 64 + (lane & 15)) * AST + (lane >> 4) * 8) * 2;
    const uint32_t boff = ((warp_n * 32 + (lane >> 4) * 8 + (lane & 7)) * AST + ((lane >> 3) & 1) * 8) * 2;

    auto compute = [&](int buf) {
        uint32_t abase = sb + buf * STAGEH * 2 + aoff;
        uint32_t bbase = sb + (buf * STAGEH + TILEH) * 2 + boff;
        #pragma unroll
        for (int ks = 0; ks < 4; ks++) {
            uint32_t koff = ks * 16 * 2;
            uint32_t a[4][4];
            #pragma unroll
            for (int mt = 0; mt < 4; mt++)
                LDSM4(a[mt][0], a[mt][1], a[mt][2], a[mt][3],
                      abase + mt * 16 * AST * 2 + koff);
            uint32_t b[4][2];
            LDSM4(b[0][0], b[0][1], b[1][0], b[1][1], bbase + koff);
            LDSM4(b[2][0], b[2][1], b[3][0], b[3][1], bbase + 16 * AST * 2 + koff);
            #pragma unroll
            for (int mt = 0; mt < 4; mt++)
                #pragma unroll
                for (int nt = 0; nt < 4; nt++)
                    mma_fp16(cc[mt][nt][0], cc[mt][nt][1], cc[mt][nt][2], cc[mt][nt][3],
                             a[mt][0], a[mt][1], a[mt][2], a[mt][3], b[nt][0], b[nt][1]);
        }
    };

    const int NK = INTER / 64;   // 32
    prefetch(0, 0); cp_commit();
    prefetch(1, 1); cp_commit();
    for (int kt = 0; kt < NK; kt++) {
        if (kt + 2 < NK) prefetch(kt + 2, (kt + 2) % NSTAGE);
        cp_commit();
        cp_wait2();
        __syncthreads();
        compute(kt % NSTAGE);
        __syncthreads();
    }

    // epilogue: scatter fp32 rows to out
    #pragma unroll
    for (int mt = 0; mt < 4; mt++) {
        int lm = warp_m * 64 + mt * 16 + gid;
        int t0 = ridx[lm];
        int t1 = ridx[lm + 8];
        #pragma unroll
        for (int nt = 0; nt < 4; nt++) {
            int col = n0 + warp_n * 32 + nt * 8 + 2 * tig;
            if (t0 >= 0) {
                float2 v = make_float2(cc[mt][nt][0], cc[mt][nt][1]);
                *(float2*)&out[(size_t)t0 * HIDDEN + col] = v;
            }
            if (t1 >= 0) {
                float2 v = make_float2(cc[mt][nt][2], cc[mt][nt][3]);
                *(float2*)&out[(size_t)t1 * HIDDEN + col] = v;
            }
        }
    }
}

// ---------------- launch ----------------
extern "C" void kernel_launch(void* const* d_in, const int* in_sizes, int n_in,
                              void* d_out, int out_size) {
    const float* x  = nullptr;
    const float* w1 = nullptr;
    const float* w2 = nullptr;
    const int*   tok = nullptr;
    for (int i = 0; i < n_in; i++) {
        long long n = in_sizes[i];
        if (n == (long long)NUM_TOKENS) tok = (const int*)d_in[i];
        else if (n == (long long)NUM_TOKENS * HIDDEN) x = (const float*)d_in[i];
        else if (n == (long long)NUM_EXPERTS * HIDDEN * 2 * INTER) w1 = (const float*)d_in[i];
        else if (n == (long long)NUM_EXPERTS * INTER * HIDDEN) w2 = (const float*)d_in[i];
    }
    float* out = (float*)d_out;

    cudaFuncSetAttribute(gemm1_kernel, cudaFuncAttributeMaxDynamicSharedMemorySize, G_SMEM);
    cudaFuncSetAttribute(gemm2_kernel, cudaFuncAttributeMaxDynamicSharedMemorySize, G_SMEM);

    zero_cnt_kernel<<<1, 32>>>();
    route_kernel<<<NUM_TOKENS / 256, 256>>>(tok);

    // preprocessing: fp16 convert (+ weight transposes to [N][K])
    convert_x_kernel<<<8192, 256>>>((const float4*)x);
    transpose_w1_kernel<<<dim3(64, 64, 8), dim3(32, 8)>>>(w1);
    transpose_w2_kernel<<<dim3(64, 32, 8), dim3(32, 8)>>>(w2);

    // gemm1: n-tiles (2048/64=32) x m-tiles (64) x experts (8)
    gemm1_kernel<<<dim3(32, 64, 8), 256, G_SMEM>>>();
    // gemm2: n-tiles (4096/128=32) x m-tiles (64) x experts (8)
    gemm2_kernel<<<dim3(32, 64, 8), 256, G_SMEM>>>(out);
}

// round 14
// speedup vs baseline: 2.3012x; 1.1193x over previous
#include <cuda_runtime.h>
#include <cuda_fp16.h>
#include <cstdint>
#include <math.h>

#define NUM_TOKENS 8192
#define HIDDEN 4096
#define NUM_EXPERTS 8
#define INTER 2048

// ---------------- device scratch (no allocs allowed) ----------------
__device__ int    g_cnt[NUM_EXPERTS];
__device__ int    g_idx[NUM_EXPERTS * NUM_TOKENS];
__device__ __half g_xh[(size_t)NUM_TOKENS * HIDDEN];                  // 67 MB
__device__ __half g_w1h[(size_t)NUM_EXPERTS * HIDDEN * 2 * INTER];    // 268 MB, [e][H][2I] (native)
__device__ __half g_w2h[(size_t)NUM_EXPERTS * INTER * HIDDEN];        // 134 MB, [e][I][H]  (native)
__device__ __half g_interh[(size_t)NUM_TOKENS * INTER];               // 33 MB

// ---------------- routing ----------------
__global__ void zero_cnt_kernel() {
    if (threadIdx.x < NUM_EXPERTS) g_cnt[threadIdx.x] = 0;
}

__global__ void route_kernel(const int* __restrict__ tok32) {
    __shared__ int s_is32;
    if (threadIdx.x == 0) {
        int any = 0;
        #pragma unroll
        for (int j = 1; j < 32; j += 2) any |= tok32[j];
        s_is32 = (any != 0);
    }
    __syncthreads();
    int i = blockIdx.x * blockDim.x + threadIdx.x;
    if (i < NUM_TOKENS) {
        int e;
        if (s_is32) e = tok32[i] & 7;
        else {
            long long t = ((const long long*)tok32)[i];
            e = (int)(t & 7);
        }
        int slot = atomicAdd(&g_cnt[e], 1);
        g_idx[e * NUM_TOKENS + slot] = i;
    }
}

// ---------------- preprocessing: streaming fp32 -> fp16 (no transpose) ----------------
__device__ __forceinline__ void cvt8(const float4* __restrict__ in, __half* __restrict__ out, size_t idx) {
    float4 v0 = in[idx * 2];
    float4 v1 = in[idx * 2 + 1];
    __half2 h0 = __floats2half2_rn(v0.x, v0.y);
    __half2 h1 = __floats2half2_rn(v0.z, v0.w);
    __half2 h2 = __floats2half2_rn(v1.x, v1.y);
    __half2 h3 = __floats2half2_rn(v1.z, v1.w);
    uint4 u;
    u.x = *(uint32_t*)&h0; u.y = *(uint32_t*)&h1;
    u.z = *(uint32_t*)&h2; u.w = *(uint32_t*)&h3;
    *(uint4*)&out[idx * 8] = u;
}

__global__ void convert_x_kernel(const float4* __restrict__ x4) {
    size_t i = (size_t)blockIdx.x * blockDim.x + threadIdx.x;   // 4194304 threads
    cvt8(x4, g_xh, i);
}
__global__ void convert_w1_kernel(const float4* __restrict__ w4) {
    size_t i = (size_t)blockIdx.x * blockDim.x + threadIdx.x;
    #pragma unroll
    for (int t = 0; t < 4; t++)
        cvt8(w4, g_w1h, i + (size_t)t * 4194304);
}
__global__ void convert_w2_kernel(const float4* __restrict__ w4) {
    size_t i = (size_t)blockIdx.x * blockDim.x + threadIdx.x;
    #pragma unroll
    for (int t = 0; t < 2; t++)
        cvt8(w4, g_w2h, i + (size_t)t * 4194304);
}

// ---------------- helpers ----------------
__device__ __forceinline__ void cp16(uint32_t dst, const void* src, bool pred) {
    int sz = pred ? 16 : 0;
    asm volatile("cp.async.cg.shared.global [%0], [%1], 16, %2;\n"
                 :: "r"(dst), "l"(src), "r"(sz));
}
__device__ __forceinline__ void cp_commit() { asm volatile("cp.async.commit_group;\n"); }
__device__ __forceinline__ void cp_wait2()  { asm volatile("cp.async.wait_group 2;\n"); }

__device__ __forceinline__ void mma_fp16(float& c0, float& c1, float& c2, float& c3,
                                         uint32_t a0, uint32_t a1, uint32_t a2, uint32_t a3,
                                         uint32_t b0, uint32_t b1) {
    asm volatile("mma.sync.aligned.m16n8k16.row.col.f32.f16.f16.f32 "
                 "{%0,%1,%2,%3}, {%4,%5,%6,%7}, {%8,%9}, {%0,%1,%2,%3};\n"
                 : "+f"(c0), "+f"(c1), "+f"(c2), "+f"(c3)
                 : "r"(a0), "r"(a1), "r"(a2), "r"(a3), "r"(b0), "r"(b1));
}

#define LDSM4(r0, r1, r2, r3, addr) \
    asm volatile("ldmatrix.sync.aligned.m8n8.x4.shared.b16 {%0,%1,%2,%3}, [%4];" \
                 : "=r"(r0), "=r"(r1), "=r"(r2), "=r"(r3) : "r"(addr))
#define LDSM4T(r0, r1, r2, r3, addr) \
    asm volatile("ldmatrix.sync.aligned.m8n8.x4.trans.shared.b16 {%0,%1,%2,%3}, [%4];" \
                 : "=r"(r0), "=r"(r1), "=r"(r2), "=r"(r3) : "r"(addr))

// ---------------- smem geometry ----------------
// BK = 32. A tile: 128 rows x 32 halves, stride 40 (80 B = 16*5, ldmatrix-aligned,
// conflict-free: 20-bank row steps). B tiles: [K=32 rows][N cols], k-major.
#define AST    40
#define ATILE  (128 * AST)            // 5120 halves
// gemm1: Bg + Bu, each 32 x 72 (N=64 + 8 pad; 144 B rows)
#define BST1   72
#define BG1    ATILE
#define BU1    (ATILE + 32 * BST1)
#define STAGE1 (ATILE + 2 * 32 * BST1)  // 9728 halves = 19456 B
// gemm2: B 32 x 136 (N=128 + 8 pad; 272 B rows)
#define BST2   136
#define BOFF2  ATILE
#define STAGE2 (ATILE + 32 * BST2)    // 9472 halves = 18944 B
#define NSTAGE 4
#define G1_SMEM (NSTAGE * STAGE1 * 2 + 512)   // ~78.3 KB
#define G2_SMEM (NSTAGE * STAGE2 * 2 + 512)   // ~76.3 KB

// ======================================================================
// GEMM1: gu = Xh_gathered @ W1h[e] (K=4096, BK=32), silu*up -> g_interh
// Tile: M=128, gate N=64 + up N=64. 8 warps: warp_m{0,1} x warp_n{0..3}.
// ======================================================================
__global__ __launch_bounds__(256, 2) void gemm1_kernel() {
    extern __shared__ __half smh[];
    int* ridx = (int*)(smh + NSTAGE * STAGE1);

    const int e   = blockIdx.z;
    const int cnt = g_cnt[e];
    const int m0  = blockIdx.y * 128;
    if (m0 >= cnt) return;
    const int n0  = blockIdx.x * 64;

    const int tid = threadIdx.x;
    if (tid < 128) {
        int m = m0 + tid;
        ridx[tid] = (m < cnt) ? g_idx[e * NUM_TOKENS + m] : -1;
    }
    __syncthreads();

    const __half* W = g_w1h + (size_t)e * HIDDEN * (2 * INTER);

    const int wid = tid >> 5, lane = tid & 31;
    const int warp_m = wid & 1, warp_n = wid >> 1;
    const int gid = lane >> 2, tig = lane & 3;

    float cg[4][2][4], cu[4][2][4];
    #pragma unroll
    for (int a = 0; a < 4; a++)
        #pragma unroll
        for (int b = 0; b < 2; b++)
            #pragma unroll
            for (int c = 0; c < 4; c++) { cg[a][b][c] = 0.f; cu[a][b][c] = 0.f; }

    // A loads: 128 rows x 4 chunks(8h) = 512 vec -> 2/thread
    const __half* asrc[2]; bool apred[2]; uint32_t adst[2];
    #pragma unroll
    for (int t = 0; t < 2; t++) {
        int vec = tid + t * 256;
        int arow = vec >> 2, acv = vec & 3;
        int r = ridx[arow];
        apred[t] = (r >= 0);
        asrc[t] = g_xh + (size_t)(apred[t] ? r : 0) * HIDDEN + acv * 8;
        adst[t] = (arow * AST + acv * 8) * 2;
    }
    // B loads: 32 k-rows x 8 chunks each for gate & up -> 1+1 per thread
    const int brow = tid >> 3, bcv = tid & 7;
    const __half* bsrc_g = W + (size_t)brow * (2 * INTER) + n0 + bcv * 8;
    const __half* bsrc_u = bsrc_g + INTER;
    const uint32_t bdst_g = (BG1 + brow * BST1 + bcv * 8) * 2;
    const uint32_t bdst_u = (BU1 + brow * BST1 + bcv * 8) * 2;

    uint32_t sb = (uint32_t)__cvta_generic_to_shared(smh);

    auto prefetch = [&](int kt) {
        int buf = kt & (NSTAGE - 1);
        int k0 = kt * 32;
        uint32_t sbb = sb + buf * STAGE1 * 2;
        #pragma unroll
        for (int t = 0; t < 2; t++) cp16(sbb + adst[t], asrc[t] + k0, apred[t]);
        size_t wko = (size_t)k0 * (2 * INTER);
        cp16(sbb + bdst_g, bsrc_g + wko, true);
        cp16(sbb + bdst_u, bsrc_u + wko, true);
    };

    // ldmatrix offsets (bytes)
    const uint32_t aoff = ((warp_m * 64 + (lane & 15)) * AST + (lane >> 4) * 8) * 2;
    const uint32_t brow_l = (lane & 7) + ((lane >> 3) & 1) * 8;     // k row within 16
    const uint32_t boff = (brow_l * BST1 + warp_n * 16 + (lane >> 4) * 8) * 2;

    auto compute = [&](int buf) {
        uint32_t abase = sb + buf * STAGE1 * 2 + aoff;
        uint32_t gbase = sb + (buf * STAGE1 + BG1) * 2 + boff;
        uint32_t ubase = sb + (buf * STAGE1 + BU1) * 2 + boff;
        #pragma unroll
        for (int ks = 0; ks < 2; ks++) {
            uint32_t ka = ks * 16 * 2;              // k halves within A row
            uint32_t kb = ks * 16 * BST1 * 2;       // k rows within B tile
            uint32_t a[4][4];
            #pragma unroll
            for (int mt = 0; mt < 4; mt++)
                LDSM4(a[mt][0], a[mt][1], a[mt][2], a[mt][3],
                      abase + mt * 16 * AST * 2 + ka);
            uint32_t bg[2][2], bu[2][2];
            LDSM4T(bg[0][0], bg[0][1], bg[1][0], bg[1][1], gbase + kb);
            LDSM4T(bu[0][0], bu[0][1], bu[1][0], bu[1][1], ubase + kb);
            #pragma unroll
            for (int mt = 0; mt < 4; mt++)
                #pragma unroll
                for (int nt = 0; nt < 2; nt++) {
                    mma_fp16(cg[mt][nt][0], cg[mt][nt][1], cg[mt][nt][2], cg[mt][nt][3],
                             a[mt][0], a[mt][1], a[mt][2], a[mt][3], bg[nt][0], bg[nt][1]);
                    mma_fp16(cu[mt][nt][0], cu[mt][nt][1], cu[mt][nt][2], cu[mt][nt][3],
                             a[mt][0], a[mt][1], a[mt][2], a[mt][3], bu[nt][0], bu[nt][1]);
                }
        }
    };

    const int NK = HIDDEN / 32;   // 128
    prefetch(0); cp_commit();
    prefetch(1); cp_commit();
    prefetch(2); cp_commit();
    for (int kt = 0; kt < NK; kt++) {
        cp_wait2();
        __syncthreads();
        compute(kt & (NSTAGE - 1));
        if (kt + 3 < NK) prefetch(kt + 3);
        cp_commit();
    }

    // epilogue: silu(gate)*up -> g_interh (fp16)
    #pragma unroll
    for (int mt = 0; mt < 4; mt++) {
        int lm = warp_m * 64 + mt * 16 + gid;
        int t0 = ridx[lm];
        int t1 = ridx[lm + 8];
        #pragma unroll
        for (int nt = 0; nt < 2; nt++) {
            int col = n0 + warp_n * 16 + nt * 8 + 2 * tig;
            if (t0 >= 0) {
                float g0 = cg[mt][nt][0], u0 = cu[mt][nt][0];
                float g1 = cg[mt][nt][1], u1 = cu[mt][nt][1];
                float v0 = g0 / (1.f + __expf(-g0)) * u0;
                float v1 = g1 / (1.f + __expf(-g1)) * u1;
                *(__half2*)&g_interh[(size_t)t0 * INTER + col] = __floats2half2_rn(v0, v1);
            }
            if (t1 >= 0) {
                float g0 = cg[mt][nt][2], u0 = cu[mt][nt][2];
                float g1 = cg[mt][nt][3], u1 = cu[mt][nt][3];
                float v0 = g0 / (1.f + __expf(-g0)) * u0;
                float v1 = g1 / (1.f + __expf(-g1)) * u1;
                *(__half2*)&g_interh[(size_t)t1 * INTER + col] = __floats2half2_rn(v0, v1);
            }
        }
    }
}

// ======================================================================
// GEMM2: out = interh_gathered @ W2h[e] (K=2048, BK=32), scatter fp32 rows.
// Tile 128 x 128. 8 warps: warp_m{0,1} x warp_n{0..3} (32 cols each).
// ======================================================================
__global__ __launch_bounds__(256, 2) void gemm2_kernel(float* __restrict__ out) {
    extern __shared__ __half smh[];
    int* ridx = (int*)(smh + NSTAGE * STAGE2);

    const int e   = blockIdx.z;
    const int cnt = g_cnt[e];
    const int m0  = blockIdx.y * 128;
    if (m0 >= cnt) return;
    const int n0  = blockIdx.x * 128;

    const int tid = threadIdx.x;
    if (tid < 128) {
        int m = m0 + tid;
        ridx[tid] = (m < cnt) ? g_idx[e * NUM_TOKENS + m] : -1;
    }
    __syncthreads();

    const __half* W = g_w2h + (size_t)e * INTER * HIDDEN;

    const int wid = tid >> 5, lane = tid & 31;
    const int warp_m = wid & 1, warp_n = wid >> 1;
    const int gid = lane >> 2, tig = lane & 3;

    float cc[4][4][4];
    #pragma unroll
    for (int a = 0; a < 4; a++)
        #pragma unroll
        for (int b = 0; b < 4; b++)
            #pragma unroll
            for (int c = 0; c < 4; c++) cc[a][b][c] = 0.f;

    const __half* asrc[2]; bool apred[2]; uint32_t adst[2];
    #pragma unroll
    for (int t = 0; t < 2; t++) {
        int vec = tid + t * 256;
        int arow = vec >> 2, acv = vec & 3;
        int r = ridx[arow];
        apred[t] = (r >= 0);
        asrc[t] = g_interh + (size_t)(apred[t] ? r : 0) * INTER + acv * 8;
        adst[t] = (arow * AST + acv * 8) * 2;
    }
    // B: 32 k-rows x 16 chunks = 512 vec -> 2/thread
    const __half* bsrc[2]; uint32_t bdst[2];
    #pragma unroll
    for (int t = 0; t < 2; t++) {
        int vec = tid + t * 256;
        int brow = vec >> 4, bcv = vec & 15;
        bsrc[t] = W + (size_t)brow * HIDDEN + n0 + bcv * 8;
        bdst[t] = (BOFF2 + brow * BST2 + bcv * 8) * 2;
    }

    uint32_t sb = (uint32_t)__cvta_generic_to_shared(smh);

    auto prefetch = [&](int kt) {
        int buf = kt & (NSTAGE - 1);
        int k0 = kt * 32;
        uint32_t sbb = sb + buf * STAGE2 * 2;
        #pragma unroll
        for (int t = 0; t < 2; t++) cp16(sbb + adst[t], asrc[t] + k0, apred[t]);
        size_t wko = (size_t)k0 * HIDDEN;
        #pragma unroll
        for (int t = 0; t < 2; t++) cp16(sbb + bdst[t], bsrc[t] + wko, true);
    };

    const uint32_t aoff = ((warp_m * 64 + (lane & 15)) * AST + (lane >> 4) * 8) * 2;
    const uint32_t brow_l = (lane & 7) + ((lane >> 3) & 1) * 8;
    const uint32_t boff = (brow_l * BST2 + warp_n * 32 + (lane >> 4) * 8) * 2;

    auto compute = [&](int buf) {
        uint32_t abase = sb + buf * STAGE2 * 2 + aoff;
        uint32_t bbase = sb + (buf * STAGE2 + BOFF2) * 2 + boff;
        #pragma unroll
        for (int ks = 0; ks < 2; ks++) {
            uint32_t ka = ks * 16 * 2;
            uint32_t kb = ks * 16 * BST2 * 2;
            uint32_t a[4][4];
            #pragma unroll
            for (int mt = 0; mt < 4; mt++)
                LDSM4(a[mt][0], a[mt][1], a[mt][2], a[mt][3],
                      abase + mt * 16 * AST * 2 + ka);
            uint32_t b[4][2];
            LDSM4T(b[0][0], b[0][1], b[1][0], b[1][1], bbase + kb);
            LDSM4T(b[2][0], b[2][1], b[3][0], b[3][1], bbase + kb + 16 * 2);
            #pragma unroll
            for (int mt = 0; mt < 4; mt++)
                #pragma unroll
                for (int nt = 0; nt < 4; nt++)
                    mma_fp16(cc[mt][nt][0], cc[mt][nt][1], cc[mt][nt][2], cc[mt][nt][3],
                             a[mt][0], a[mt][1], a[mt][2], a[mt][3], b[nt][0], b[nt][1]);
        }
    };

    const int NK = INTER / 32;   // 64
    prefetch(0); cp_commit();
    prefetch(1); cp_commit();
    prefetch(2); cp_commit();
    for (int kt = 0; kt < NK; kt++) {
        cp_wait2();
        __syncthreads();
        compute(kt & (NSTAGE - 1));
        if (kt + 3 < NK) prefetch(kt + 3);
        cp_commit();
    }

    // epilogue: scatter fp32 rows to out
    #pragma unroll
    for (int mt = 0; mt < 4; mt++) {
        int lm = warp_m * 64 + mt * 16 + gid;
        int t0 = ridx[lm];
        int t1 = ridx[lm + 8];
        #pragma unroll
        for (int nt = 0; nt < 4; nt++) {
            int col = n0 + warp_n * 32 + nt * 8 + 2 * tig;
            if (t0 >= 0) {
                float2 v = make_float2(cc[mt][nt][0], cc[mt][nt][1]);
                *(float2*)&out[(size_t)t0 * HIDDEN + col] = v;
            }
            if (t1 >= 0) {
                float2 v = make_float2(cc[mt][nt][2], cc[mt][nt][3]);
                *(float2*)&out[(size_t)t1 * HIDDEN + col] = v;
            }
        }
    }
}

// ---------------- launch ----------------
extern "C" void kernel_launch(void* const* d_in, const int* in_sizes, int n_in,
                              void* d_out, int out_size) {
    const float* x  = nullptr;
    const float* w1 = nullptr;
    const float* w2 = nullptr;
    const int*   tok = nullptr;
    for (int i = 0; i < n_in; i++) {
        long long n = in_sizes[i];
        if (n == (long long)NUM_TOKENS) tok = (const int*)d_in[i];
        else if (n == (long long)NUM_TOKENS * HIDDEN) x = (const float*)d_in[i];
        else if (n == (long long)NUM_EXPERTS * HIDDEN * 2 * INTER) w1 = (const float*)d_in[i];
        else if (n == (long long)NUM_EXPERTS * INTER * HIDDEN) w2 = (const float*)d_in[i];
    }
    float* out = (float*)d_out;

    cudaFuncSetAttribute(gemm1_kernel, cudaFuncAttributeMaxDynamicSharedMemorySize, G1_SMEM);
    cudaFuncSetAttribute(gemm2_kernel, cudaFuncAttributeMaxDynamicSharedMemorySize, G2_SMEM);

    zero_cnt_kernel<<<1, 32>>>();
    route_kernel<<<NUM_TOKENS / 256, 256>>>(tok);

    // preprocessing: streaming fp16 converts (no transposes)
    convert_x_kernel<<<16384, 256>>>((const float4*)x);
    convert_w1_kernel<<<16384, 256>>>((const float4*)w1);
    convert_w2_kernel<<<16384, 256>>>((const float4*)w2);

    // gemm1: n-tiles (2048/64=32) x m-tiles (64) x experts (8)
    gemm1_kernel<<<dim3(32, 64, 8), 256, G1_SMEM>>>();
    // gemm2: n-tiles (4096/128=32) x m-tiles (64) x experts (8)
    gemm2_kernel<<<dim3(32, 64, 8), 256, G2_SMEM>>>(out);
}